// round 12
// baseline (speedup 1.0000x reference)
#include <cuda_runtime.h>
#include <math.h>

// AttentionST: attention pooling, fused single pass (R7 structure + f32x2 FMA).
// E: [B, S, D] fp32, w_att: [D], w_pred: [D], b_pred: scalar -> out: [B]
// logit[b] = sum_s softmax(E[b]·w_att)[s] * (E[b,s]·w_pred) + b_pred; out = sigmoid(logit)
//
// DRAM-bound at the ~6.6 TB/s path-independent LTS cap; ~99% of the 402MB
// byte floor. This round halves main-loop FMA issues via Blackwell packed
// fma.rn.f32x2 (96 -> 48 per 2-row iteration). E loaded as ulonglong2 so the
// LDG.128 register pairs feed the packed FMAs with zero pack movs.

constexpr int D = 768;
constexpr int S = 512;
constexpr int NTHREADS = 256;
constexpr int NWARPS = NTHREADS / 32;
constexpr int F4_PER_ROW = D / 4;             // 192 16B-chunks per row
constexpr int FL = F4_PER_ROW / 32;           // 6 chunks per lane per row

using u64 = unsigned long long;

__device__ __forceinline__ u64 pack2(float lo, float hi) {
    u64 r;
    asm("mov.b64 %0, {%1, %2};" : "=l"(r) : "f"(lo), "f"(hi));
    return r;
}
__device__ __forceinline__ void unpack2(u64 v, float& lo, float& hi) {
    asm("mov.b64 {%0, %1}, %2;" : "=f"(lo), "=f"(hi) : "l"(v));
}
__device__ __forceinline__ u64 fma2(u64 a, u64 b, u64 c) {
    u64 d;
    asm("fma.rn.f32x2 %0, %1, %2, %3;" : "=l"(d) : "l"(a), "l"(b), "l"(c));
    return d;
}

__global__ __launch_bounds__(NTHREADS, 2) void attn_pool_kernel(
    const float* __restrict__ E,
    const float* __restrict__ w_att,
    const float* __restrict__ w_pred,
    const float* __restrict__ b_pred,
    float* __restrict__ out)
{
    __shared__ float2 s_tp[S];        // (score, pred-dot) per position

    const int b    = blockIdx.x;
    const int tid  = threadIdx.x;
    const int warp = tid >> 5;
    const int lane = tid & 31;

    // Prefetch the bias early so its DRAM latency hides under the stream.
    float bias = 0.f;
    if (warp == 0 && lane == 0) bias = b_pred[0];

    // Weight vectors register-resident as packed f32x2 pairs (48 regs).
    u64 waL[FL], waH[FL], wpL[FL], wpH[FL];
    #pragma unroll
    for (int j = 0; j < FL; j++) {
        float4 a = reinterpret_cast<const float4*>(w_att)[j * 32 + lane];
        float4 p = reinterpret_cast<const float4*>(w_pred)[j * 32 + lane];
        waL[j] = pack2(a.x, a.y); waH[j] = pack2(a.z, a.w);
        wpL[j] = pack2(p.x, p.y); wpH[j] = pack2(p.z, p.w);
    }

    const ulonglong2* Eb =
        reinterpret_cast<const ulonglong2*>(E) + (size_t)b * S * F4_PER_ROW;

    // Pass 1: each warp handles 2 adjacent s-rows per iteration.
    // 12 independent LDG.128 (evict-first) in flight; 48 packed f32x2 FMAs.
    for (int s = 2 * warp; s < S; s += 2 * NWARPS) {
        const ulonglong2* r0 = Eb + (size_t)s * F4_PER_ROW;
        const ulonglong2* r1 = r0 + F4_PER_ROW;

        ulonglong2 v0[FL], v1[FL];
        #pragma unroll
        for (int j = 0; j < FL; j++) v0[j] = __ldcs(r0 + j * 32 + lane);
        #pragma unroll
        for (int j = 0; j < FL; j++) v1[j] = __ldcs(r1 + j * 32 + lane);

        const u64 Z = 0ull;  // packed (0.f, 0.f)
        u64 t0a = Z, t0b = Z, p0a = Z, p0b = Z;
        u64 t1a = Z, t1b = Z, p1a = Z, p1b = Z;
        #pragma unroll
        for (int j = 0; j < FL; j++) {
            t0a = fma2(v0[j].x, waL[j], t0a);
            t0b = fma2(v0[j].y, waH[j], t0b);
            p0a = fma2(v0[j].x, wpL[j], p0a);
            p0b = fma2(v0[j].y, wpH[j], p0b);
            t1a = fma2(v1[j].x, waL[j], t1a);
            t1b = fma2(v1[j].y, waH[j], t1b);
            p1a = fma2(v1[j].x, wpL[j], p1a);
            p1b = fma2(v1[j].y, wpH[j], p1b);
        }
        float x, y, z, w;
        unpack2(t0a, x, y); unpack2(t0b, z, w); float t0 = (x + z) + (y + w);
        unpack2(p0a, x, y); unpack2(p0b, z, w); float p0 = (x + z) + (y + w);
        unpack2(t1a, x, y); unpack2(t1b, z, w); float t1 = (x + z) + (y + w);
        unpack2(p1a, x, y); unpack2(p1b, z, w); float p1 = (x + z) + (y + w);

        #pragma unroll
        for (int o = 16; o; o >>= 1) {
            t0 += __shfl_xor_sync(0xffffffffu, t0, o);
            p0 += __shfl_xor_sync(0xffffffffu, p0, o);
            t1 += __shfl_xor_sync(0xffffffffu, t1, o);
            p1 += __shfl_xor_sync(0xffffffffu, p1, o);
        }
        if (lane == 0) {
            // s is even: s_tp[s], s_tp[s+1] are one aligned 16B slot -> STS.128.
            *reinterpret_cast<float4*>(&s_tp[s]) = make_float4(t0, p0, t1, p1);
        }
    }
    __syncthreads();

    // Epilogue: warps 1..7 retire immediately; warp 0 does the whole softmax
    // register-resident (16 float2 per lane).
    if (warp != 0) return;

    float2 v[16];
    #pragma unroll
    for (int k = 0; k < 16; k++) v[k] = s_tp[k * 32 + lane];

    float m = -INFINITY;
    #pragma unroll
    for (int k = 0; k < 16; k++) m = fmaxf(m, v[k].x);
    #pragma unroll
    for (int o = 16; o; o >>= 1) m = fmaxf(m, __shfl_xor_sync(0xffffffffu, m, o));

    float se = 0.f, sep = 0.f;
    #pragma unroll
    for (int k = 0; k < 16; k++) {
        float e = __expf(v[k].x - m);
        se += e;
        sep = fmaf(e, v[k].y, sep);
    }
    #pragma unroll
    for (int o = 16; o; o >>= 1) {
        se  += __shfl_xor_sync(0xffffffffu, se, o);
        sep += __shfl_xor_sync(0xffffffffu, sep, o);
    }

    if (lane == 0) {
        float logit = sep / se + bias;
        out[b] = 1.f / (1.f + __expf(-logit));
    }
}

extern "C" void kernel_launch(void* const* d_in, const int* in_sizes, int n_in,
                              void* d_out, int out_size)
{
    const float* E      = (const float*)d_in[0];
    const float* w_att  = (const float*)d_in[1];
    const float* w_pred = (const float*)d_in[2];
    const float* b_pred = (const float*)d_in[3];
    float* out = (float*)d_out;

    const int B = in_sizes[0] / (S * D);
    attn_pool_kernel<<<B, NTHREADS>>>(E, w_att, w_pred, b_pred, out);
}

// round 13
// speedup vs baseline: 1.0005x; 1.0005x over previous
#include <cuda_runtime.h>
#include <math.h>

// AttentionST: attention pooling, fused single pass. FINAL (R7 structure).
// E: [B, S, D] fp32, w_att: [D], w_pred: [D], b_pred: scalar -> out: [B]
// logit[b] = sum_s softmax(E[b]·w_att)[s] * (E[b,s]·w_pred) + b_pred; out = sigmoid(logit)
//
// Session evidence (R1-R12): DRAM-bound at the path-independent ~6.6 TB/s
// chip LTS cap. Seven structural variants plateau at 61.1-61.7 us (ncu),
// ~99% of the 402MB/6.64TB/s byte floor. R12's f32x2 control experiment
// (issue 15.9%->11.8%, duration unchanged) proves issue capacity is not
// binding. Best-measured variant: one CTA per batch row, 2 s-rows per warp
// per iteration (12 front-batched LDG.128 evict-first), register-resident
// weights, single barrier, warp-0 register-resident epilogue.

constexpr int D = 768;
constexpr int S = 512;
constexpr int NTHREADS = 256;
constexpr int NWARPS = NTHREADS / 32;
constexpr int F4_PER_ROW = D / 4;             // 192
constexpr int FL = F4_PER_ROW / 32;           // 6 float4 per lane per row

__global__ __launch_bounds__(NTHREADS, 2) void attn_pool_kernel(
    const float* __restrict__ E,
    const float* __restrict__ w_att,
    const float* __restrict__ w_pred,
    const float* __restrict__ b_pred,
    float* __restrict__ out)
{
    __shared__ float2 s_tp[S];        // (score, pred-dot) per position

    const int b    = blockIdx.x;
    const int tid  = threadIdx.x;
    const int warp = tid >> 5;
    const int lane = tid & 31;

    // Prefetch the bias early so its DRAM latency hides under the stream.
    float bias = 0.f;
    if (warp == 0 && lane == 0) bias = b_pred[0];

    // Both weight vectors register-resident (48 regs), fixed per lane.
    float4 wa[FL], wp[FL];
    #pragma unroll
    for (int j = 0; j < FL; j++) {
        wa[j] = reinterpret_cast<const float4*>(w_att)[j * 32 + lane];
        wp[j] = reinterpret_cast<const float4*>(w_pred)[j * 32 + lane];
    }

    const float4* Eb = reinterpret_cast<const float4*>(E) + (size_t)b * S * F4_PER_ROW;

    // Pass 1: each warp handles 2 adjacent s-rows per iteration.
    // 12 independent LDG.128 (evict-first) in flight; 4 interleaved FMA chains.
    for (int s = 2 * warp; s < S; s += 2 * NWARPS) {
        const float4* r0 = Eb + (size_t)s * F4_PER_ROW;
        const float4* r1 = r0 + F4_PER_ROW;

        float4 v0[FL], v1[FL];
        #pragma unroll
        for (int j = 0; j < FL; j++) v0[j] = __ldcs(r0 + j * 32 + lane);
        #pragma unroll
        for (int j = 0; j < FL; j++) v1[j] = __ldcs(r1 + j * 32 + lane);

        float t0 = 0.f, p0 = 0.f, t1 = 0.f, p1 = 0.f;
        float t0b = 0.f, p0b = 0.f, t1b = 0.f, p1b = 0.f;
        #pragma unroll
        for (int j = 0; j < FL; j++) {
            t0  = fmaf(v0[j].x, wa[j].x, t0);
            t0b = fmaf(v0[j].y, wa[j].y, t0b);
            t0  = fmaf(v0[j].z, wa[j].z, t0);
            t0b = fmaf(v0[j].w, wa[j].w, t0b);
            p0  = fmaf(v0[j].x, wp[j].x, p0);
            p0b = fmaf(v0[j].y, wp[j].y, p0b);
            p0  = fmaf(v0[j].z, wp[j].z, p0);
            p0b = fmaf(v0[j].w, wp[j].w, p0b);
            t1  = fmaf(v1[j].x, wa[j].x, t1);
            t1b = fmaf(v1[j].y, wa[j].y, t1b);
            t1  = fmaf(v1[j].z, wa[j].z, t1);
            t1b = fmaf(v1[j].w, wa[j].w, t1b);
            p1  = fmaf(v1[j].x, wp[j].x, p1);
            p1b = fmaf(v1[j].y, wp[j].y, p1b);
            p1  = fmaf(v1[j].z, wp[j].z, p1);
            p1b = fmaf(v1[j].w, wp[j].w, p1b);
        }
        t0 += t0b; p0 += p0b; t1 += t1b; p1 += p1b;

        #pragma unroll
        for (int o = 16; o; o >>= 1) {
            t0 += __shfl_xor_sync(0xffffffffu, t0, o);
            p0 += __shfl_xor_sync(0xffffffffu, p0, o);
            t1 += __shfl_xor_sync(0xffffffffu, t1, o);
            p1 += __shfl_xor_sync(0xffffffffu, p1, o);
        }
        if (lane == 0) {
            // s is even: s_tp[s], s_tp[s+1] are one aligned 16B slot -> STS.128.
            *reinterpret_cast<float4*>(&s_tp[s]) = make_float4(t0, p0, t1, p1);
        }
    }
    __syncthreads();

    // Epilogue: warps 1..7 retire immediately; warp 0 does the whole softmax
    // register-resident (16 float2 per lane).
    if (warp != 0) return;

    float2 v[16];
    #pragma unroll
    for (int k = 0; k < 16; k++) v[k] = s_tp[k * 32 + lane];

    float m = -INFINITY;
    #pragma unroll
    for (int k = 0; k < 16; k++) m = fmaxf(m, v[k].x);
    #pragma unroll
    for (int o = 16; o; o >>= 1) m = fmaxf(m, __shfl_xor_sync(0xffffffffu, m, o));

    float se = 0.f, sep = 0.f;
    #pragma unroll
    for (int k = 0; k < 16; k++) {
        float e = __expf(v[k].x - m);
        se += e;
        sep = fmaf(e, v[k].y, sep);
    }
    #pragma unroll
    for (int o = 16; o; o >>= 1) {
        se  += __shfl_xor_sync(0xffffffffu, se, o);
        sep += __shfl_xor_sync(0xffffffffu, sep, o);
    }

    if (lane == 0) {
        float logit = sep / se + bias;
        out[b] = 1.f / (1.f + __expf(-logit));
    }
}

extern "C" void kernel_launch(void* const* d_in, const int* in_sizes, int n_in,
                              void* d_out, int out_size)
{
    const float* E      = (const float*)d_in[0];
    const float* w_att  = (const float*)d_in[1];
    const float* w_pred = (const float*)d_in[2];
    const float* b_pred = (const float*)d_in[3];
    float* out = (float*)d_out;

    const int B = in_sizes[0] / (S * D);
    attn_pool_kernel<<<B, NTHREADS>>>(E, w_att, w_pred, b_pred, out);
}